// round 15
// baseline (speedup 1.0000x reference)
#include <cuda_runtime.h>
#include <cuda_fp16.h>
#include <cstdint>
#include <cstddef>

// Problem constants
#define BATCH 8
#define SEQ   1024
#define EMB   1024
#define NHEAD 16
#define DHEAD 64
#define E3    3072   // 3*EMB

// Scratch: fp16 copies of x and W, fp16 QKV projection output
__device__ __half g_xh[(size_t)BATCH * SEQ * EMB];
__device__ __half g_wh[(size_t)E3 * EMB];
__device__ __half g_qkvh[(size_t)BATCH * SEQ * E3];

// ---------------------------------------------------------------------------
// Helpers
// ---------------------------------------------------------------------------
__device__ __forceinline__ uint32_t h2_bits(__half2 h) {
    return *reinterpret_cast<uint32_t*>(&h);
}

__device__ __forceinline__ __half2 bits_h2(uint32_t u) {
    return *reinterpret_cast<__half2*>(&u);
}

__device__ __forceinline__ uint32_t smem_u32(const void* p) {
    uint32_t a;
    asm("{ .reg .u64 t; cvta.to.shared.u64 t, %1; cvt.u32.u64 %0, t; }"
        : "=r"(a) : "l"(p));
    return a;
}

__device__ __forceinline__ void cp16(uint32_t dst, const void* src) {
    asm volatile("cp.async.cg.shared.global [%0], [%1], 16;"
                 :: "r"(dst), "l"(src) : "memory");
}

__device__ __forceinline__ float ex2f(float x) {
    float r;
    asm("ex2.approx.ftz.f32 %0, %1;" : "=f"(r) : "f"(x));
    return r;
}

// mma.sync m16n8k16 f16 with fp32 accum: D += A*B, row.col
__device__ __forceinline__ void mma_f16(float* d, const uint32_t* a, const uint32_t* b) {
    asm volatile(
        "mma.sync.aligned.m16n8k16.row.col.f32.f16.f16.f32 "
        "{%0,%1,%2,%3}, {%4,%5,%6,%7}, {%8,%9}, {%0,%1,%2,%3};"
        : "+f"(d[0]), "+f"(d[1]), "+f"(d[2]), "+f"(d[3])
        : "r"(a[0]), "r"(a[1]), "r"(a[2]), "r"(a[3]),
          "r"(b[0]), "r"(b[1]));
}

__device__ __forceinline__ void ldsm_x4(uint32_t* r, uint32_t addr) {
    asm volatile("ldmatrix.sync.aligned.m8n8.x4.shared.b16 {%0,%1,%2,%3}, [%4];"
                 : "=r"(r[0]), "=r"(r[1]), "=r"(r[2]), "=r"(r[3]) : "r"(addr));
}

__device__ __forceinline__ void ldsm_x4_t(uint32_t* r, uint32_t addr) {
    asm volatile("ldmatrix.sync.aligned.m8n8.x4.trans.shared.b16 {%0,%1,%2,%3}, [%4];"
                 : "=r"(r[0]), "=r"(r[1]), "=r"(r[2]), "=r"(r[3]) : "r"(addr));
}

__device__ __forceinline__ void ldsm_x2(uint32_t* r, uint32_t addr) {
    asm volatile("ldmatrix.sync.aligned.m8n8.x2.shared.b16 {%0,%1}, [%2];"
                 : "=r"(r[0]), "=r"(r[1]) : "r"(addr));
}

__device__ __forceinline__ void ldsm_x2_t(uint32_t* r, uint32_t addr) {
    asm volatile("ldmatrix.sync.aligned.m8n8.x2.trans.shared.b16 {%0,%1}, [%2];"
                 : "=r"(r[0]), "=r"(r[1]) : "r"(addr));
}

// ---------------------------------------------------------------------------
// Robust length read (int64 vs int32 l buffer)
// ---------------------------------------------------------------------------
__device__ __forceinline__ int get_len(const int* __restrict__ p, int b) {
    bool is64 = ((p[1] | p[3] | p[5] | p[7]) == 0);
    return is64 ? p[2 * b] : p[b];
}

// ---------------------------------------------------------------------------
// Pre-pass: fp32 -> fp16 for x and W, grid-stride; x rows >= L[b] skipped.
// ---------------------------------------------------------------------------
#define N4X ((BATCH * SEQ * EMB) / 4)    // 2097152
#define N4W ((E3 * EMB) / 4)             // 786432
#define TOTAL4 (N4X + N4W)

__global__ void to_half_both(const float4* __restrict__ x, uint2* __restrict__ xo,
                             const float4* __restrict__ w, uint2* __restrict__ wo,
                             const int* __restrict__ lens) {
    for (int i = blockIdx.x * blockDim.x + threadIdx.x; i < TOTAL4;
         i += gridDim.x * blockDim.x) {
        const float4* in;
        uint2* out;
        int j;
        if (i < N4X) {
            const int token = i >> 8;                 // 256 float4 per row
            if ((token & 1023) >= get_len(lens, token >> 10)) continue;
            in = x; out = xo; j = i;
        } else {
            in = w; out = wo; j = i - N4X;
        }
        float4 v = in[j];
        uint2 o;
        o.x = h2_bits(__floats2half2_rn(v.x, v.y));
        o.y = h2_bits(__floats2half2_rn(v.z, v.w));
        out[j] = o;
    }
}

// ---------------------------------------------------------------------------
// Kernel A: QKV projection GEMM (mma.sync f16, fp32 accum) — unchanged (R13)
// CTA 128x128, 256 threads, BK=64, 3-stage pipeline, 2 CTAs/SM.
// ---------------------------------------------------------------------------
#define BM 128
#define BN 128
#define BKH 64
#define NKI (1024 / BKH)    // 16
#define NSTG 3
#define RPG 72
#define STG_HALVES ((BM + BN) * RPG)                  // 18432
#define SMEM_GEMM_TOTAL (NSTG * STG_HALVES * 2)       // 110592 bytes

__global__ __launch_bounds__(256, 2) void qkv_gemm_h(
    const __half* __restrict__ A,
    const __half* __restrict__ W,
    const float* __restrict__ bias,
    const int* __restrict__ lens,
    __half* __restrict__ C)
{
    extern __shared__ __half smh[];

    const int bm = blockIdx.y * BM;
    {
        const int lb = get_len(lens, bm >> 10);
        if ((bm & 1023) >= lb) return;
    }

    const int tid  = threadIdx.x;
    const int wid  = tid >> 5;
    const int lane = tid & 31;
    const int g = lane >> 2;
    const int c = lane & 3;
    const int wm = wid >> 2;
    const int wn = wid & 3;
    const int bn = blockIdx.x * BN;

    float acc[4][4][4];
#pragma unroll
    for (int mi = 0; mi < 4; mi++)
#pragma unroll
        for (int ni = 0; ni < 4; ni++)
#pragma unroll
            for (int r = 0; r < 4; r++) acc[mi][ni][r] = 0.f;

    const uint32_t sm_u = smem_u32(smh);

    const uint32_t a_base = ((uint32_t)((wm * 64 + (lane & 15)) * RPG
                                        + ((lane >> 4) << 3))) * 2;
    const uint32_t b_base = ((uint32_t)((BM + wn * 32 + (lane & 7)) * RPG
                                        + (((lane >> 3) & 1) << 3))) * 2;

#define LOAD_STAGE(kt, s)                                                      \
    {                                                                          \
        const int kof = (kt) * BKH;                                            \
        const uint32_t dst = sm_u + (uint32_t)(s) * (STG_HALVES * 2);          \
        _Pragma("unroll")                                                      \
        for (int f = 0; f < 8; f++) {                                          \
            const int idx = f * 256 + tid;                                     \
            if (idx < 1024) {                                                  \
                const int row = idx >> 3;                                      \
                const int ch  = (idx & 7) << 3;                                \
                cp16(dst + (row * RPG + ch) * 2,                               \
                     A + (size_t)(bm + row) * 1024 + kof + ch);                \
            } else {                                                           \
                const int gdx = idx - 1024;                                    \
                const int row = gdx >> 3;                                      \
                const int ch  = (gdx & 7) << 3;                                \
                cp16(dst + ((BM + row) * RPG + ch) * 2,                        \
                     W + (size_t)(bn + row) * 1024 + kof + ch);                \
            }                                                                  \
        }                                                                      \
        asm volatile("cp.async.commit_group;" ::: "memory");                   \
    }

    LOAD_STAGE(0, 0);
    LOAD_STAGE(1, 1);

#pragma unroll 1
    for (int kt = 0; kt < NKI; kt++) {
        if (kt < NKI - 1) asm volatile("cp.async.wait_group 1;" ::: "memory");
        else              asm volatile("cp.async.wait_group 0;" ::: "memory");
        __syncthreads();

        if (kt + 2 < NKI) {
            LOAD_STAGE(kt + 2, (kt + 2) % NSTG);
        }

        const uint32_t stg = sm_u + (uint32_t)(kt % NSTG) * (STG_HALVES * 2);
        const uint32_t aB = stg + a_base;
        const uint32_t bB = stg + b_base;

#pragma unroll
        for (int kk = 0; kk < 4; kk++) {
            uint32_t af[4][4], bf[4][2];
#pragma unroll
            for (int mi = 0; mi < 4; mi++)
                ldsm_x4(af[mi], aB + (uint32_t)((mi * 16 * RPG + kk * 16) * 2));
#pragma unroll
            for (int ni = 0; ni < 4; ni++)
                ldsm_x2(bf[ni], bB + (uint32_t)((ni * 8 * RPG + kk * 16) * 2));
#pragma unroll
            for (int mi = 0; mi < 4; mi++)
#pragma unroll
                for (int ni = 0; ni < 4; ni++)
                    mma_f16(acc[mi][ni], af[mi], bf[ni]);
        }
    }

#pragma unroll
    for (int mi = 0; mi < 4; mi++) {
        const int r0 = bm + wm * 64 + mi * 16 + g;
#pragma unroll
        for (int ni = 0; ni < 4; ni++) {
            const int col = bn + wn * 32 + ni * 8 + c * 2;
            const float bx = __ldg(bias + col);
            const float by = __ldg(bias + col + 1);
            __half2 v0 = __floats2half2_rn(acc[mi][ni][0] + bx, acc[mi][ni][1] + by);
            __half2 v1 = __floats2half2_rn(acc[mi][ni][2] + bx, acc[mi][ni][3] + by);
            *(__half2*)(C + (size_t)r0 * E3 + col) = v0;
            *(__half2*)(C + (size_t)(r0 + 8) * E3 + col) = v1;
        }
    }
}

// ---------------------------------------------------------------------------
// Kernel B: flash attention, Q-tile = 128 rows, 256 threads (8 warps),
// 2 CTAs/SM via launch_bounds. Halves KV traffic vs 64-row tiles.
// fp16 operands, fp32 accum, no online max, log2-domain scores + ex2,
// tensor-core softmax denominator via ones-column in V, heavy-first qt.
// Warp w owns q rows [qbase+16w, qbase+16w+16); skips tiles before its rows.
// ---------------------------------------------------------------------------
#define QT 128
#define ATT_TH 4608                       // 64*72 halves per KV buffer
#define QP_HALVES (QT * 72)               // 9216
#define ATT_SMEM ((4 * ATT_TH + QP_HALVES) * 2)   // 55296 bytes

__global__ __launch_bounds__(256, 2) void attn_h(
    const __half* __restrict__ qkv,
    const int* __restrict__ lens,
    float* __restrict__ out)
{
    extern __shared__ __half smh[];
    __half* QP = smh + 4 * ATT_TH;        // 128 rows x 72 halves

    const int tid  = threadIdx.x;
    const int wid  = tid >> 5;
    const int lane = tid & 31;
    const int g = lane >> 2;
    const int c = lane & 3;

    // heavy-first: high qt (more k-tiles) scheduled earliest
    const int qt = (int)(gridDim.x - 1 - blockIdx.x);
    const int h  = blockIdx.y;
    const int b  = blockIdx.z;
    const int L  = get_len(lens, b);
    const int qbase = qt * QT;

    float* outp = out + ((size_t)(b * SEQ + qbase)) * EMB + h * DHEAD;

    if (qbase >= L) {   // fully masked q tile -> zeros (128 rows x 64 cols)
        float4 z = make_float4(0.f, 0.f, 0.f, 0.f);
#pragma unroll
        for (int t = 0; t < 8; t++) {
            int idx = t * 256 + tid;
            int row = idx >> 4, c4 = (idx & 15) << 2;
            *(float4*)(outp + (size_t)row * EMB + c4) = z;
        }
        return;
    }

    // load Q tile (128 rows x 64 halves) into QP
    {
        const __half* qgp = qkv + ((size_t)(b * SEQ + qbase)) * E3 + h * DHEAD;
#pragma unroll
        for (int t = 0; t < 4; t++) {
            int idx = t * 256 + tid;
            int row = idx >> 3, ch = (idx & 7) << 3;
            *(uint4*)&QP[row * 72 + ch] = *(const uint4*)(qgp + (size_t)row * E3 + ch);
        }
    }

    const uint32_t sm_u = smem_u32(smh);
    const uint32_t QP_u = smem_u32(QP);
    const uint32_t Pw_u = QP_u + (uint32_t)(wid * 16 * 72) * 2;

    // ones-column init: V buffers col 64 = 1.0, cols 65..71 = 0 (both buffers)
    if (tid < 128) {
        const uint32_t vbase = sm_u + (uint32_t)((2 + (tid >> 6)) * ATT_TH) * 2;
        const uint32_t addr = vbase + (uint32_t)(((tid & 63) * 72 + 64) * 2);
        uint4 onesv = make_uint4(0x3C00u, 0u, 0u, 0u);
        asm volatile("st.shared.v4.b32 [%0], {%1,%2,%3,%4};"
                     :: "r"(addr), "r"(onesv.x), "r"(onesv.y),
                        "r"(onesv.z), "r"(onesv.w) : "memory");
    }
    __syncthreads();

    const uint32_t a_off = ((uint32_t)((lane & 15) * 72 + ((lane >> 4) << 3))) * 2;
    const uint32_t k_off = ((uint32_t)(((lane & 7) + ((lane >> 4) << 3)) * 72
                                       + (((lane >> 3) & 1) << 3))) * 2;
    const uint32_t ones_row_off = ((uint32_t)((lane & 15) * 72 + 64)) * 2;

    // Q fragments via ldmatrix, scaled by log2(e)/32 (log2-domain scores)
    uint32_t qf[4][4];
    {
        const __half2 qs = __float2half2_rn(0.04508422f);   // log2(e)/32
#pragma unroll
        for (int kk = 0; kk < 4; kk++) {
            ldsm_x4(qf[kk], Pw_u + a_off + kk * 32);
#pragma unroll
            for (int r = 0; r < 4; r++)
                qf[kk][r] = h2_bits(__hmul2(bits_h2(qf[kk][r]), qs));
        }
    }

    const int ktmax = min(2 * qt + 1, (L - 1) >> 6);
    const int wrow0 = qbase + wid * 16;       // warp's first q row (global)

#define KV_LOAD(kt, buf)                                                        \
    {                                                                           \
        const __half* kgp = qkv + ((size_t)(b * SEQ + (kt) * 64)) * E3          \
                            + EMB + h * DHEAD;                                  \
        const uint32_t dK = sm_u + (uint32_t)((buf) * ATT_TH) * 2;              \
        const uint32_t dV = sm_u + (uint32_t)((2 + (buf)) * ATT_TH) * 2;        \
        _Pragma("unroll")                                                       \
        for (int t = 0; t < 4; t++) {                                           \
            int idx = t * 256 + tid;                                            \
            if (idx < 512) {                                                    \
                int row = idx >> 3, ch = (idx & 7) << 3;                        \
                cp16(dK + (row * 72 + ch) * 2, kgp + (size_t)row * E3 + ch);    \
            } else {                                                            \
                int jdx = idx - 512;                                            \
                int row = jdx >> 3, ch = (jdx & 7) << 3;                        \
                cp16(dV + (row * 72 + ch) * 2,                                  \
                     kgp + (size_t)row * E3 + EMB + ch);                        \
            }                                                                   \
        }                                                                       \
        asm volatile("cp.async.commit_group;" ::: "memory");                    \
    }

    KV_LOAD(0, 0);

    float lacc[4] = {0.f, 0.f, 0.f, 0.f};
    float oacc[8][4];
#pragma unroll
    for (int dt = 0; dt < 8; dt++)
#pragma unroll
        for (int r = 0; r < 4; r++) oacc[dt][r] = 0.f;

    __half* Pw = QP + (wid * 16) * 72;

#pragma unroll 1
    for (int kt = 0; kt <= ktmax; kt++) {
        if (kt < ktmax) KV_LOAD(kt + 1, (kt + 1) & 1);
        if (kt < ktmax) asm volatile("cp.async.wait_group 1;" ::: "memory");
        else            asm volatile("cp.async.wait_group 0;" ::: "memory");
        __syncthreads();

        // warp-uniform: this k tile only matters if it reaches the warp's rows
        if (kt * 64 <= wrow0 + 15) {
            const uint32_t Kp_u = sm_u + (uint32_t)((kt & 1) * ATT_TH) * 2;
            const uint32_t Vp_u = sm_u + (uint32_t)((2 + (kt & 1)) * ATT_TH) * 2;

            // ---- S = Q @ K^T (log2 domain) ----
            float sacc[8][4];
#pragma unroll
            for (int nt = 0; nt < 8; nt++)
#pragma unroll
                for (int r = 0; r < 4; r++) sacc[nt][r] = 0.f;

#pragma unroll
            for (int kk = 0; kk < 4; kk++) {
#pragma unroll
                for (int nt2 = 0; nt2 < 4; nt2++) {
                    uint32_t bf4[4];
                    ldsm_x4(bf4, Kp_u + k_off + (uint32_t)(nt2 * 2304 + kk * 32));
                    mma_f16(sacc[2 * nt2],     qf[kk], bf4);
                    mma_f16(sacc[2 * nt2 + 1], qf[kk], bf4 + 2);
                }
            }

            // ---- causal mask (partial tile for this warp) ----
            if (kt * 64 + 63 > wrow0) {
                const int r0g = wrow0 + g;
                const int r1g = r0g + 8;
#pragma unroll
                for (int nt = 0; nt < 8; nt++) {
                    const int cg = kt * 64 + nt * 8 + 2 * c;
                    if (cg > r0g)     sacc[nt][0] = -1e30f;
                    if (cg + 1 > r0g) sacc[nt][1] = -1e30f;
                    if (cg > r1g)     sacc[nt][2] = -1e30f;
                    if (cg + 1 > r1g) sacc[nt][3] = -1e30f;
                }
            }

            // ---- P = 2^S ----
#pragma unroll
            for (int nt = 0; nt < 8; nt++) {
                const float p0 = ex2f(sacc[nt][0]);
                const float p1 = ex2f(sacc[nt][1]);
                const float p2 = ex2f(sacc[nt][2]);
                const float p3 = ex2f(sacc[nt][3]);
                *(__half2*)&Pw[g * 72 + nt * 8 + 2 * c]       = __floats2half2_rn(p0, p1);
                *(__half2*)&Pw[(g + 8) * 72 + nt * 8 + 2 * c] = __floats2half2_rn(p2, p3);
            }
            __syncwarp();

            // ---- O += P @ V, plus l += P @ ones (tensor-core row sums) ----
#pragma unroll
            for (int kk = 0; kk < 4; kk++) {
                uint32_t pf[4];
                ldsm_x4(pf, Pw_u + a_off + kk * 32);
#pragma unroll
                for (int dtp = 0; dtp < 4; dtp++) {
                    uint32_t bf4[4];
                    ldsm_x4_t(bf4, Vp_u + a_off + (uint32_t)(kk * 2304 + dtp * 32));
                    mma_f16(oacc[2 * dtp],     pf, bf4);
                    mma_f16(oacc[2 * dtp + 1], pf, bf4 + 2);
                }
                uint32_t bo[2];
                ldsm_x2_t(bo, Vp_u + ones_row_off + (uint32_t)(kk * 2304));
                mma_f16(lacc, pf, bo);
            }
        }
        __syncthreads();
    }

    // ---- epilogue: l lives in the c==0 lane of each quad (col 64) ----
    const float l0 = __shfl_sync(0xFFFFFFFF, lacc[0], lane & ~3);
    const float l1 = __shfl_sync(0xFFFFFFFF, lacc[2], lane & ~3);
    const float inv0 = 1.0f / l0;
    const float inv1 = 1.0f / l1;
    const int q0row = qbase + wid * 16 + g;
    const int q1row = q0row + 8;
    const bool v0 = (q0row < L);
    const bool v1 = (q1row < L);
    float* o0 = out + ((size_t)(b * SEQ + q0row)) * EMB + h * DHEAD;
    float* o1 = out + ((size_t)(b * SEQ + q1row)) * EMB + h * DHEAD;
#pragma unroll
    for (int dt = 0; dt < 8; dt++) {
        const int col = dt * 8 + 2 * c;
        float2 r0 = v0 ? make_float2(oacc[dt][0] * inv0, oacc[dt][1] * inv0)
                       : make_float2(0.f, 0.f);
        float2 r1 = v1 ? make_float2(oacc[dt][2] * inv1, oacc[dt][3] * inv1)
                       : make_float2(0.f, 0.f);
        *(float2*)(o0 + col) = r0;
        *(float2*)(o1 + col) = r1;
    }
}

// ---------------------------------------------------------------------------
// Launch
// ---------------------------------------------------------------------------
extern "C" void kernel_launch(void* const* d_in, const int* in_sizes, int n_in,
                              void* d_out, int out_size) {
    const float* x = nullptr;
    const int*   l = nullptr;
    const float* W = nullptr;
    const float* bias = nullptr;
    for (int i = 0; i < n_in; i++) {
        switch (in_sizes[i]) {
            case 8388608: x    = (const float*)d_in[i]; break;
            case 8:       l    = (const int*)d_in[i];   break;
            case 3145728: W    = (const float*)d_in[i]; break;
            case 3072:    bias = (const float*)d_in[i]; break;
            default: break;
        }
    }
    float* out = (float*)d_out;

    __half *xh = nullptr, *wh = nullptr, *qkvh = nullptr;
    cudaGetSymbolAddress((void**)&xh,   g_xh);
    cudaGetSymbolAddress((void**)&wh,   g_wh);
    cudaGetSymbolAddress((void**)&qkvh, g_qkvh);

    static bool attr_set = false;
    if (!attr_set) {
        cudaFuncSetAttribute(qkv_gemm_h,
                             cudaFuncAttributeMaxDynamicSharedMemorySize,
                             SMEM_GEMM_TOTAL);
        cudaFuncSetAttribute(attn_h,
                             cudaFuncAttributeMaxDynamicSharedMemorySize,
                             ATT_SMEM);
        attr_set = true;
    }

    // fp32 -> fp16 conversion of x (valid rows only) and W, grid-stride
    to_half_both<<<1536, 256>>>(
        (const float4*)x, (uint2*)xh, (const float4*)W, (uint2*)wh, l);

    dim3 gg(E3 / BN, (BATCH * SEQ) / BM);     // (24, 64)
    qkv_gemm_h<<<gg, 256, SMEM_GEMM_TOTAL>>>(xh, wh, bias, l, qkvh);

    dim3 ga(SEQ / QT, NHEAD, BATCH);          // (8, 16, 8)
    attn_h<<<ga, 256, ATT_SMEM>>>(qkvh, l, out);
}

// round 16
// speedup vs baseline: 1.0673x; 1.0673x over previous
#include <cuda_runtime.h>
#include <cuda_fp16.h>
#include <cstdint>
#include <cstddef>

// Problem constants
#define BATCH 8
#define SEQ   1024
#define EMB   1024
#define NHEAD 16
#define DHEAD 64
#define E3    3072   // 3*EMB

// Scratch: fp16 copies of x and W, fp16 QKV projection output
__device__ __half g_xh[(size_t)BATCH * SEQ * EMB];
__device__ __half g_wh[(size_t)E3 * EMB];
__device__ __half g_qkvh[(size_t)BATCH * SEQ * E3];

// ---------------------------------------------------------------------------
// Helpers
// ---------------------------------------------------------------------------
__device__ __forceinline__ uint32_t h2_bits(__half2 h) {
    return *reinterpret_cast<uint32_t*>(&h);
}

__device__ __forceinline__ __half2 bits_h2(uint32_t u) {
    return *reinterpret_cast<__half2*>(&u);
}

__device__ __forceinline__ uint32_t smem_u32(const void* p) {
    uint32_t a;
    asm("{ .reg .u64 t; cvta.to.shared.u64 t, %1; cvt.u32.u64 %0, t; }"
        : "=r"(a) : "l"(p));
    return a;
}

__device__ __forceinline__ void cp16(uint32_t dst, const void* src) {
    asm volatile("cp.async.cg.shared.global [%0], [%1], 16;"
                 :: "r"(dst), "l"(src) : "memory");
}

__device__ __forceinline__ float ex2f(float x) {
    float r;
    asm("ex2.approx.ftz.f32 %0, %1;" : "=f"(r) : "f"(x));
    return r;
}

// mma.sync m16n8k16 f16 with fp32 accum: D += A*B, row.col
__device__ __forceinline__ void mma_f16(float* d, const uint32_t* a, const uint32_t* b) {
    asm volatile(
        "mma.sync.aligned.m16n8k16.row.col.f32.f16.f16.f32 "
        "{%0,%1,%2,%3}, {%4,%5,%6,%7}, {%8,%9}, {%0,%1,%2,%3};"
        : "+f"(d[0]), "+f"(d[1]), "+f"(d[2]), "+f"(d[3])
        : "r"(a[0]), "r"(a[1]), "r"(a[2]), "r"(a[3]),
          "r"(b[0]), "r"(b[1]));
}

__device__ __forceinline__ void ldsm_x4(uint32_t* r, uint32_t addr) {
    asm volatile("ldmatrix.sync.aligned.m8n8.x4.shared.b16 {%0,%1,%2,%3}, [%4];"
                 : "=r"(r[0]), "=r"(r[1]), "=r"(r[2]), "=r"(r[3]) : "r"(addr));
}

__device__ __forceinline__ void ldsm_x4_t(uint32_t* r, uint32_t addr) {
    asm volatile("ldmatrix.sync.aligned.m8n8.x4.trans.shared.b16 {%0,%1,%2,%3}, [%4];"
                 : "=r"(r[0]), "=r"(r[1]), "=r"(r[2]), "=r"(r[3]) : "r"(addr));
}

__device__ __forceinline__ void ldsm_x2(uint32_t* r, uint32_t addr) {
    asm volatile("ldmatrix.sync.aligned.m8n8.x2.shared.b16 {%0,%1}, [%2];"
                 : "=r"(r[0]), "=r"(r[1]) : "r"(addr));
}

__device__ __forceinline__ void ldsm_x2_t(uint32_t* r, uint32_t addr) {
    asm volatile("ldmatrix.sync.aligned.m8n8.x2.trans.shared.b16 {%0,%1}, [%2];"
                 : "=r"(r[0]), "=r"(r[1]) : "r"(addr));
}

// ---------------------------------------------------------------------------
// Robust length read (int64 vs int32 l buffer)
// ---------------------------------------------------------------------------
__device__ __forceinline__ int get_len(const int* __restrict__ p, int b) {
    bool is64 = ((p[1] | p[3] | p[5] | p[7]) == 0);
    return is64 ? p[2 * b] : p[b];
}

// ---------------------------------------------------------------------------
// Pre-pass: fp32 -> fp16 for x and W in one launch; x rows >= L[b] skipped.
// (R14-proven shape: one element per thread.)
// ---------------------------------------------------------------------------
#define N4X ((BATCH * SEQ * EMB) / 4)    // 2097152
#define N4W ((E3 * EMB) / 4)             // 786432

__global__ void to_half_both(const float4* __restrict__ x, uint2* __restrict__ xo,
                             const float4* __restrict__ w, uint2* __restrict__ wo,
                             const int* __restrict__ lens) {
    int i = blockIdx.x * blockDim.x + threadIdx.x;
    const float4* in;
    uint2* out;
    int j;
    if (i < N4X) {
        const int token = i >> 8;                     // 256 float4 per row
        if ((token & 1023) >= get_len(lens, token >> 10)) return;
        in = x; out = xo; j = i;
    }
    else if (i < N4X + N4W) { in = w; out = wo; j = i - N4X; }
    else return;
    float4 v = in[j];
    uint2 o;
    o.x = h2_bits(__floats2half2_rn(v.x, v.y));
    o.y = h2_bits(__floats2half2_rn(v.z, v.w));
    out[j] = o;
}

// ---------------------------------------------------------------------------
// Kernel A: QKV projection GEMM (mma.sync f16, fp32 accum) — unchanged (R13)
// CTA 128x128, 256 threads, BK=64, 3-stage pipeline, 2 CTAs/SM.
// ---------------------------------------------------------------------------
#define BM 128
#define BN 128
#define BKH 64
#define NKI (1024 / BKH)    // 16
#define NSTG 3
#define RPG 72
#define STG_HALVES ((BM + BN) * RPG)                  // 18432
#define SMEM_GEMM_TOTAL (NSTG * STG_HALVES * 2)       // 110592 bytes

__global__ __launch_bounds__(256, 2) void qkv_gemm_h(
    const __half* __restrict__ A,
    const __half* __restrict__ W,
    const float* __restrict__ bias,
    const int* __restrict__ lens,
    __half* __restrict__ C)
{
    extern __shared__ __half smh[];

    const int bm = blockIdx.y * BM;
    {
        const int lb = get_len(lens, bm >> 10);
        if ((bm & 1023) >= lb) return;
    }

    const int tid  = threadIdx.x;
    const int wid  = tid >> 5;
    const int lane = tid & 31;
    const int g = lane >> 2;
    const int c = lane & 3;
    const int wm = wid >> 2;
    const int wn = wid & 3;
    const int bn = blockIdx.x * BN;

    float acc[4][4][4];
#pragma unroll
    for (int mi = 0; mi < 4; mi++)
#pragma unroll
        for (int ni = 0; ni < 4; ni++)
#pragma unroll
            for (int r = 0; r < 4; r++) acc[mi][ni][r] = 0.f;

    const uint32_t sm_u = smem_u32(smh);

    const uint32_t a_base = ((uint32_t)((wm * 64 + (lane & 15)) * RPG
                                        + ((lane >> 4) << 3))) * 2;
    const uint32_t b_base = ((uint32_t)((BM + wn * 32 + (lane & 7)) * RPG
                                        + (((lane >> 3) & 1) << 3))) * 2;

#define LOAD_STAGE(kt, s)                                                      \
    {                                                                          \
        const int kof = (kt) * BKH;                                            \
        const uint32_t dst = sm_u + (uint32_t)(s) * (STG_HALVES * 2);          \
        _Pragma("unroll")                                                      \
        for (int f = 0; f < 8; f++) {                                          \
            const int idx = f * 256 + tid;                                     \
            if (idx < 1024) {                                                  \
                const int row = idx >> 3;                                      \
                const int ch  = (idx & 7) << 3;                                \
                cp16(dst + (row * RPG + ch) * 2,                               \
                     A + (size_t)(bm + row) * 1024 + kof + ch);                \
            } else {                                                           \
                const int gdx = idx - 1024;                                    \
                const int row = gdx >> 3;                                      \
                const int ch  = (gdx & 7) << 3;                                \
                cp16(dst + ((BM + row) * RPG + ch) * 2,                        \
                     W + (size_t)(bn + row) * 1024 + kof + ch);                \
            }                                                                  \
        }                                                                      \
        asm volatile("cp.async.commit_group;" ::: "memory");                   \
    }

    LOAD_STAGE(0, 0);
    LOAD_STAGE(1, 1);

#pragma unroll 1
    for (int kt = 0; kt < NKI; kt++) {
        if (kt < NKI - 1) asm volatile("cp.async.wait_group 1;" ::: "memory");
        else              asm volatile("cp.async.wait_group 0;" ::: "memory");
        __syncthreads();

        if (kt + 2 < NKI) {
            LOAD_STAGE(kt + 2, (kt + 2) % NSTG);
        }

        const uint32_t stg = sm_u + (uint32_t)(kt % NSTG) * (STG_HALVES * 2);
        const uint32_t aB = stg + a_base;
        const uint32_t bB = stg + b_base;

#pragma unroll
        for (int kk = 0; kk < 4; kk++) {
            uint32_t af[4][4], bf[4][2];
#pragma unroll
            for (int mi = 0; mi < 4; mi++)
                ldsm_x4(af[mi], aB + (uint32_t)((mi * 16 * RPG + kk * 16) * 2));
#pragma unroll
            for (int ni = 0; ni < 4; ni++)
                ldsm_x2(bf[ni], bB + (uint32_t)((ni * 8 * RPG + kk * 16) * 2));
#pragma unroll
            for (int mi = 0; mi < 4; mi++)
#pragma unroll
                for (int ni = 0; ni < 4; ni++)
                    mma_f16(acc[mi][ni], af[mi], bf[ni]);
        }
    }

#pragma unroll
    for (int mi = 0; mi < 4; mi++) {
        const int r0 = bm + wm * 64 + mi * 16 + g;
#pragma unroll
        for (int ni = 0; ni < 4; ni++) {
            const int col = bn + wn * 32 + ni * 8 + c * 2;
            const float bx = __ldg(bias + col);
            const float by = __ldg(bias + col + 1);
            __half2 v0 = __floats2half2_rn(acc[mi][ni][0] + bx, acc[mi][ni][1] + by);
            __half2 v1 = __floats2half2_rn(acc[mi][ni][2] + bx, acc[mi][ni][3] + by);
            *(__half2*)(C + (size_t)r0 * E3 + col) = v0;
            *(__half2*)(C + (size_t)(r0 + 8) * E3 + col) = v1;
        }
    }
}

// ---------------------------------------------------------------------------
// Kernel B: flash attention, R14 shape (64-row q tile, 4 warps) with a
// 3-buffer KV ring so the end-of-tile __syncthreads is REMOVED:
// buffer (kt+1)%3 written at iter kt was last read at iter kt-2, and every
// warp is provably past the top-sync of iter kt-1 -> no race, 1 barrier/tile,
// warps may drift and overlap S and PV phases.
// fp16 operands, fp32 accum, no online max, log2-domain scores + ex2,
// tensor-core softmax denominator via ones-column in V, heavy-first qt.
// ---------------------------------------------------------------------------
#define ATT_TH 4608                       // 64*72 halves per buffer
#define NKV 3
#define QPOFF (2 * NKV * ATT_TH)          // after K[3] and V[3]
#define ATT_SMEM ((QPOFF + ATT_TH) * 2)   // 64512 bytes

__global__ __launch_bounds__(128, 3) void attn_h(
    const __half* __restrict__ qkv,
    const int* __restrict__ lens,
    float* __restrict__ out)
{
    extern __shared__ __half smh[];
    __half* QP = smh + QPOFF;

    const int tid  = threadIdx.x;
    const int wid  = tid >> 5;
    const int lane = tid & 31;
    const int g = lane >> 2;
    const int c = lane & 3;

    // heavy-first: high qt (more k-tiles) scheduled earliest
    const int qt = (int)(gridDim.x - 1 - blockIdx.x);
    const int h  = blockIdx.y;
    const int b  = blockIdx.z;
    const int L  = get_len(lens, b);
    const int qbase = qt * 64;

    float* outp = out + ((size_t)(b * SEQ + qbase)) * EMB + h * DHEAD;

    if (qbase >= L) {
        float4 z = make_float4(0.f, 0.f, 0.f, 0.f);
#pragma unroll
        for (int t = 0; t < 8; t++) {
            int idx = t * 128 + tid;
            int row = idx >> 4, c4 = (idx & 15) << 2;
            *(float4*)(outp + (size_t)row * EMB + c4) = z;
        }
        return;
    }

    // load Q tile (64 rows x 64 halves) into QP
    {
        const __half* qgp = qkv + ((size_t)(b * SEQ + qbase)) * E3 + h * DHEAD;
#pragma unroll
        for (int t = 0; t < 4; t++) {
            int idx = t * 128 + tid;
            int row = idx >> 3, ch = (idx & 7) << 3;
            *(uint4*)&QP[row * 72 + ch] = *(const uint4*)(qgp + (size_t)row * E3 + ch);
        }
    }

    const uint32_t sm_u = smem_u32(smh);
    const uint32_t QP_u = smem_u32(QP);
    const uint32_t Pw_u = QP_u + (uint32_t)(wid * 16 * 72) * 2;

    // ones-column init: V buffers col 64 = 1.0, cols 65..71 = 0 (3 buffers,
    // 64 rows each = 192 rows; 128 threads cover 2 buffers, then 64 more)
    {
#pragma unroll
        for (int t = 0; t < 2; t++) {
            int idx = t * 128 + tid;
            if (idx < NKV * 64) {
                const uint32_t vbase = sm_u
                    + (uint32_t)((NKV + (idx >> 6)) * ATT_TH) * 2;
                const uint32_t addr = vbase + (uint32_t)(((idx & 63) * 72 + 64) * 2);
                asm volatile("st.shared.v4.b32 [%0], {%1,%2,%3,%4};"
                             :: "r"(addr), "r"(0x3C00u), "r"(0u), "r"(0u), "r"(0u)
                             : "memory");
            }
        }
    }
    __syncthreads();

    const uint32_t a_off = ((uint32_t)((lane & 15) * 72 + ((lane >> 4) << 3))) * 2;
    const uint32_t k_off = ((uint32_t)(((lane & 7) + ((lane >> 4) << 3)) * 72
                                       + (((lane >> 3) & 1) << 3))) * 2;
    const uint32_t ones_row_off = ((uint32_t)((lane & 15) * 72 + 64)) * 2;

    // Q fragments via ldmatrix, scaled by log2(e)/32 (log2-domain scores)
    uint32_t qf[4][4];
    {
        const __half2 qs = __float2half2_rn(0.04508422f);   // log2(e)/32
#pragma unroll
        for (int kk = 0; kk < 4; kk++) {
            ldsm_x4(qf[kk], Pw_u + a_off + kk * 32);
#pragma unroll
            for (int r = 0; r < 4; r++)
                qf[kk][r] = h2_bits(__hmul2(bits_h2(qf[kk][r]), qs));
        }
    }

    const int ktmax = min(qt, (L - 1) >> 6);

#define KV_LOAD(kt, buf)                                                        \
    {                                                                           \
        const __half* kgp = qkv + ((size_t)(b * SEQ + (kt) * 64)) * E3          \
                            + EMB + h * DHEAD;                                  \
        const uint32_t dK = sm_u + (uint32_t)((buf) * ATT_TH) * 2;              \
        const uint32_t dV = sm_u + (uint32_t)((NKV + (buf)) * ATT_TH) * 2;      \
        _Pragma("unroll")                                                       \
        for (int t = 0; t < 8; t++) {                                           \
            int idx = t * 128 + tid;                                            \
            if (idx < 512) {                                                    \
                int row = idx >> 3, ch = (idx & 7) << 3;                        \
                cp16(dK + (row * 72 + ch) * 2, kgp + (size_t)row * E3 + ch);    \
            } else {                                                            \
                int jdx = idx - 512;                                            \
                int row = jdx >> 3, ch = (jdx & 7) << 3;                        \
                cp16(dV + (row * 72 + ch) * 2,                                  \
                     kgp + (size_t)row * E3 + EMB + ch);                        \
            }                                                                   \
        }                                                                       \
        asm volatile("cp.async.commit_group;" ::: "memory");                    \
    }

    KV_LOAD(0, 0);

    float lacc[4] = {0.f, 0.f, 0.f, 0.f};
    float oacc[8][4];
#pragma unroll
    for (int dt = 0; dt < 8; dt++)
#pragma unroll
        for (int r = 0; r < 4; r++) oacc[dt][r] = 0.f;

    __half* Pw = QP + (wid * 16) * 72;
    int buf = 0, nbuf = 1;

#pragma unroll 1
    for (int kt = 0; kt <= ktmax; kt++) {
        // prefetch next tile into the 3-ring (safe: that buffer was last read
        // at iter kt-2, and all warps are past the top-sync of iter kt-1)
        if (kt < ktmax) KV_LOAD(kt + 1, nbuf);
        if (kt < ktmax) asm volatile("cp.async.wait_group 1;" ::: "memory");
        else            asm volatile("cp.async.wait_group 0;" ::: "memory");
        __syncthreads();   // single barrier per tile

        const uint32_t Kp_u = sm_u + (uint32_t)(buf * ATT_TH) * 2;
        const uint32_t Vp_u = sm_u + (uint32_t)((NKV + buf) * ATT_TH) * 2;

        // ---- S = Q @ K^T (log2 domain) ----
        float sacc[8][4];
#pragma unroll
        for (int nt = 0; nt < 8; nt++)
#pragma unroll
            for (int r = 0; r < 4; r++) sacc[nt][r] = 0.f;

#pragma unroll
        for (int kk = 0; kk < 4; kk++) {
#pragma unroll
            for (int nt2 = 0; nt2 < 4; nt2++) {
                uint32_t bf4[4];
                ldsm_x4(bf4, Kp_u + k_off + (uint32_t)(nt2 * 2304 + kk * 32));
                mma_f16(sacc[2 * nt2],     qf[kk], bf4);
                mma_f16(sacc[2 * nt2 + 1], qf[kk], bf4 + 2);
            }
        }

        // ---- causal mask (diagonal tile only) ----
        if (kt == qt) {
            const int lr0 = wid * 16 + g;
            const int lr1 = lr0 + 8;
#pragma unroll
            for (int nt = 0; nt < 8; nt++) {
                const int col0 = nt * 8 + 2 * c;
                if (col0 > lr0)     sacc[nt][0] = -1e30f;
                if (col0 + 1 > lr0) sacc[nt][1] = -1e30f;
                if (col0 > lr1)     sacc[nt][2] = -1e30f;
                if (col0 + 1 > lr1) sacc[nt][3] = -1e30f;
            }
        }

        // ---- P = 2^S ----
#pragma unroll
        for (int nt = 0; nt < 8; nt++) {
            const float p0 = ex2f(sacc[nt][0]);
            const float p1 = ex2f(sacc[nt][1]);
            const float p2 = ex2f(sacc[nt][2]);
            const float p3 = ex2f(sacc[nt][3]);
            *(__half2*)&Pw[g * 72 + nt * 8 + 2 * c]       = __floats2half2_rn(p0, p1);
            *(__half2*)&Pw[(g + 8) * 72 + nt * 8 + 2 * c] = __floats2half2_rn(p2, p3);
        }
        __syncwarp();

        // ---- O += P @ V, plus l += P @ ones (tensor-core row sums) ----
#pragma unroll
        for (int kk = 0; kk < 4; kk++) {
            uint32_t pf[4];
            ldsm_x4(pf, Pw_u + a_off + kk * 32);
#pragma unroll
            for (int dtp = 0; dtp < 4; dtp++) {
                uint32_t bf4[4];
                ldsm_x4_t(bf4, Vp_u + a_off + (uint32_t)(kk * 2304 + dtp * 32));
                mma_f16(oacc[2 * dtp],     pf, bf4);
                mma_f16(oacc[2 * dtp + 1], pf, bf4 + 2);
            }
            uint32_t bo[2];
            ldsm_x2_t(bo, Vp_u + ones_row_off + (uint32_t)(kk * 2304));
            mma_f16(lacc, pf, bo);
        }
        // NO end-of-tile __syncthreads: 3-buffer ring makes reuse safe.

        buf = nbuf;
        nbuf = (nbuf == NKV - 1) ? 0 : nbuf + 1;
    }

    // ---- epilogue: l lives in the c==0 lane of each quad (col 64) ----
    const float l0 = __shfl_sync(0xFFFFFFFF, lacc[0], lane & ~3);
    const float l1 = __shfl_sync(0xFFFFFFFF, lacc[2], lane & ~3);
    const float inv0 = 1.0f / l0;
    const float inv1 = 1.0f / l1;
    const int q0row = qbase + wid * 16 + g;
    const int q1row = q0row + 8;
    const bool v0 = (q0row < L);
    const bool v1 = (q1row < L);
    float* o0 = out + ((size_t)(b * SEQ + q0row)) * EMB + h * DHEAD;
    float* o1 = out + ((size_t)(b * SEQ + q1row)) * EMB + h * DHEAD;
#pragma unroll
    for (int dt = 0; dt < 8; dt++) {
        const int col = dt * 8 + 2 * c;
        float2 r0 = v0 ? make_float2(oacc[dt][0] * inv0, oacc[dt][1] * inv0)
                       : make_float2(0.f, 0.f);
        float2 r1 = v1 ? make_float2(oacc[dt][2] * inv1, oacc[dt][3] * inv1)
                       : make_float2(0.f, 0.f);
        *(float2*)(o0 + col) = r0;
        *(float2*)(o1 + col) = r1;
    }
}

// ---------------------------------------------------------------------------
// Launch
// ---------------------------------------------------------------------------
extern "C" void kernel_launch(void* const* d_in, const int* in_sizes, int n_in,
                              void* d_out, int out_size) {
    const float* x = nullptr;
    const int*   l = nullptr;
    const float* W = nullptr;
    const float* bias = nullptr;
    for (int i = 0; i < n_in; i++) {
        switch (in_sizes[i]) {
            case 8388608: x    = (const float*)d_in[i]; break;
            case 8:       l    = (const int*)d_in[i];   break;
            case 3145728: W    = (const float*)d_in[i]; break;
            case 3072:    bias = (const float*)d_in[i]; break;
            default: break;
        }
    }
    float* out = (float*)d_out;

    __half *xh = nullptr, *wh = nullptr, *qkvh = nullptr;
    cudaGetSymbolAddress((void**)&xh,   g_xh);
    cudaGetSymbolAddress((void**)&wh,   g_wh);
    cudaGetSymbolAddress((void**)&qkvh, g_qkvh);

    static bool attr_set = false;
    if (!attr_set) {
        cudaFuncSetAttribute(qkv_gemm_h,
                             cudaFuncAttributeMaxDynamicSharedMemorySize,
                             SMEM_GEMM_TOTAL);
        cudaFuncSetAttribute(attn_h,
                             cudaFuncAttributeMaxDynamicSharedMemorySize,
                             ATT_SMEM);
        attr_set = true;
    }

    // fp32 -> fp16 conversion of x (valid rows only) and W (single launch)
    {
        const int total = N4X + N4W;
        to_half_both<<<(total + 255) / 256, 256>>>(
            (const float4*)x, (uint2*)xh, (const float4*)W, (uint2*)wh, l);
    }

    dim3 gg(E3 / BN, (BATCH * SEQ) / BM);     // (24, 64)
    qkv_gemm_h<<<gg, 256, SMEM_GEMM_TOTAL>>>(xh, wh, bias, l, qkvh);

    dim3 ga(SEQ / 64, NHEAD, BATCH);          // (16, 16, 8)
    attn_h<<<ga, 128, ATT_SMEM>>>(qkvh, l, out);
}

// round 17
// speedup vs baseline: 1.0819x; 1.0137x over previous
#include <cuda_runtime.h>
#include <cuda_fp16.h>
#include <cstdint>
#include <cstddef>

// Problem constants
#define BATCH 8
#define SEQ   1024
#define EMB   1024
#define NHEAD 16
#define DHEAD 64
#define E3    3072   // 3*EMB

// Scratch: fp16 copies of x and W, fp16 QKV projection output
__device__ __half g_xh[(size_t)BATCH * SEQ * EMB];
__device__ __half g_wh[(size_t)E3 * EMB];
__device__ __half g_qkvh[(size_t)BATCH * SEQ * E3];

// ---------------------------------------------------------------------------
// Helpers
// ---------------------------------------------------------------------------
__device__ __forceinline__ uint32_t h2_bits(__half2 h) {
    return *reinterpret_cast<uint32_t*>(&h);
}

__device__ __forceinline__ __half2 bits_h2(uint32_t u) {
    return *reinterpret_cast<__half2*>(&u);
}

__device__ __forceinline__ uint32_t smem_u32(const void* p) {
    uint32_t a;
    asm("{ .reg .u64 t; cvta.to.shared.u64 t, %1; cvt.u32.u64 %0, t; }"
        : "=r"(a) : "l"(p));
    return a;
}

__device__ __forceinline__ void cp16(uint32_t dst, const void* src) {
    asm volatile("cp.async.cg.shared.global [%0], [%1], 16;"
                 :: "r"(dst), "l"(src) : "memory");
}

__device__ __forceinline__ float ex2f(float x) {
    float r;
    asm("ex2.approx.ftz.f32 %0, %1;" : "=f"(r) : "f"(x));
    return r;
}

// mma.sync m16n8k16 f16 with fp32 accum: D += A*B, row.col
__device__ __forceinline__ void mma_f16(float* d, const uint32_t* a, const uint32_t* b) {
    asm volatile(
        "mma.sync.aligned.m16n8k16.row.col.f32.f16.f16.f32 "
        "{%0,%1,%2,%3}, {%4,%5,%6,%7}, {%8,%9}, {%0,%1,%2,%3};"
        : "+f"(d[0]), "+f"(d[1]), "+f"(d[2]), "+f"(d[3])
        : "r"(a[0]), "r"(a[1]), "r"(a[2]), "r"(a[3]),
          "r"(b[0]), "r"(b[1]));
}

__device__ __forceinline__ void ldsm_x4(uint32_t* r, uint32_t addr) {
    asm volatile("ldmatrix.sync.aligned.m8n8.x4.shared.b16 {%0,%1,%2,%3}, [%4];"
                 : "=r"(r[0]), "=r"(r[1]), "=r"(r[2]), "=r"(r[3]) : "r"(addr));
}

__device__ __forceinline__ void ldsm_x4_t(uint32_t* r, uint32_t addr) {
    asm volatile("ldmatrix.sync.aligned.m8n8.x4.trans.shared.b16 {%0,%1,%2,%3}, [%4];"
                 : "=r"(r[0]), "=r"(r[1]), "=r"(r[2]), "=r"(r[3]) : "r"(addr));
}

__device__ __forceinline__ void ldsm_x2_t(uint32_t* r, uint32_t addr) {
    asm volatile("ldmatrix.sync.aligned.m8n8.x2.trans.shared.b16 {%0,%1}, [%2];"
                 : "=r"(r[0]), "=r"(r[1]) : "r"(addr));
}

// ---------------------------------------------------------------------------
// Robust length read (int64 vs int32 l buffer)
// ---------------------------------------------------------------------------
__device__ __forceinline__ int get_len(const int* __restrict__ p, int b) {
    bool is64 = ((p[1] | p[3] | p[5] | p[7]) == 0);
    return is64 ? p[2 * b] : p[b];
}

// ---------------------------------------------------------------------------
// Pre-pass: fp32 -> fp16 for x and W in one launch; x rows >= L[b] skipped.
// ---------------------------------------------------------------------------
#define N4X ((BATCH * SEQ * EMB) / 4)    // 2097152
#define N4W ((E3 * EMB) / 4)             // 786432

__global__ void to_half_both(const float4* __restrict__ x, uint2* __restrict__ xo,
                             const float4* __restrict__ w, uint2* __restrict__ wo,
                             const int* __restrict__ lens) {
    int i = blockIdx.x * blockDim.x + threadIdx.x;
    const float4* in;
    uint2* out;
    int j;
    if (i < N4X) {
        const int token = i >> 8;                     // 256 float4 per row
        if ((token & 1023) >= get_len(lens, token >> 10)) return;
        in = x; out = xo; j = i;
    }
    else if (i < N4X + N4W) { in = w; out = wo; j = i - N4X; }
    else return;
    float4 v = in[j];
    uint2 o;
    o.x = h2_bits(__floats2half2_rn(v.x, v.y));
    o.y = h2_bits(__floats2half2_rn(v.z, v.w));
    out[j] = o;
}

// ---------------------------------------------------------------------------
// Kernel A: QKV projection GEMM (mma.sync f16, fp32 accum)
// CTA 128x128, 256 threads, BK=64, 3-stage pipeline, 2 CTAs/SM.
// B fragments now via ldmatrix.x4 (2 n8-fragments per op) using the lane
// mapping proven in the attention kernel -> 25% fewer LDSM per k-iter.
// ---------------------------------------------------------------------------
#define BM 128
#define BN 128
#define BKH 64
#define NKI (1024 / BKH)    // 16
#define NSTG 3
#define RPG 72
#define STG_HALVES ((BM + BN) * RPG)                  // 18432
#define SMEM_GEMM_TOTAL (NSTG * STG_HALVES * 2)       // 110592 bytes

__global__ __launch_bounds__(256, 2) void qkv_gemm_h(
    const __half* __restrict__ A,
    const __half* __restrict__ W,
    const float* __restrict__ bias,
    const int* __restrict__ lens,
    __half* __restrict__ C)
{
    extern __shared__ __half smh[];

    const int bm = blockIdx.y * BM;
    {
        const int lb = get_len(lens, bm >> 10);
        if ((bm & 1023) >= lb) return;
    }

    const int tid  = threadIdx.x;
    const int wid  = tid >> 5;
    const int lane = tid & 31;
    const int g = lane >> 2;
    const int c = lane & 3;
    const int wm = wid >> 2;
    const int wn = wid & 3;
    const int bn = blockIdx.x * BN;

    float acc[4][4][4];
#pragma unroll
    for (int mi = 0; mi < 4; mi++)
#pragma unroll
        for (int ni = 0; ni < 4; ni++)
#pragma unroll
            for (int r = 0; r < 4; r++) acc[mi][ni][r] = 0.f;

    const uint32_t sm_u = smem_u32(smh);

    const uint32_t a_base = ((uint32_t)((wm * 64 + (lane & 15)) * RPG
                                        + ((lane >> 4) << 3))) * 2;
    // B x4 lane mapping (attention-proven): row = (lane&7) + ((lane>>4)<<3),
    // k-col8 = (lane>>3)&1. One ldsm_x4 = B-fragments for n8 pair.
    const uint32_t b_base = ((uint32_t)((BM + wn * 32 + (lane & 7)
                                         + ((lane >> 4) << 3)) * RPG
                                        + (((lane >> 3) & 1) << 3))) * 2;

#define LOAD_STAGE(kt, s)                                                      \
    {                                                                          \
        const int kof = (kt) * BKH;                                            \
        const uint32_t dst = sm_u + (uint32_t)(s) * (STG_HALVES * 2);          \
        _Pragma("unroll")                                                      \
        for (int f = 0; f < 8; f++) {                                          \
            const int idx = f * 256 + tid;                                     \
            if (idx < 1024) {                                                  \
                const int row = idx >> 3;                                      \
                const int ch  = (idx & 7) << 3;                                \
                cp16(dst + (row * RPG + ch) * 2,                               \
                     A + (size_t)(bm + row) * 1024 + kof + ch);                \
            } else {                                                           \
                const int gdx = idx - 1024;                                    \
                const int row = gdx >> 3;                                      \
                const int ch  = (gdx & 7) << 3;                                \
                cp16(dst + ((BM + row) * RPG + ch) * 2,                        \
                     W + (size_t)(bn + row) * 1024 + kof + ch);                \
            }                                                                  \
        }                                                                      \
        asm volatile("cp.async.commit_group;" ::: "memory");                   \
    }

    LOAD_STAGE(0, 0);
    LOAD_STAGE(1, 1);

#pragma unroll 1
    for (int kt = 0; kt < NKI; kt++) {
        if (kt < NKI - 1) asm volatile("cp.async.wait_group 1;" ::: "memory");
        else              asm volatile("cp.async.wait_group 0;" ::: "memory");
        __syncthreads();

        if (kt + 2 < NKI) {
            LOAD_STAGE(kt + 2, (kt + 2) % NSTG);
        }

        const uint32_t stg = sm_u + (uint32_t)(kt % NSTG) * (STG_HALVES * 2);
        const uint32_t aB = stg + a_base;
        const uint32_t bB = stg + b_base;

#pragma unroll
        for (int kk = 0; kk < 4; kk++) {
            uint32_t af[4][4], bfq[2][4];
#pragma unroll
            for (int mi = 0; mi < 4; mi++)
                ldsm_x4(af[mi], aB + (uint32_t)((mi * 16 * RPG + kk * 16) * 2));
#pragma unroll
            for (int n2 = 0; n2 < 2; n2++)
                ldsm_x4(bfq[n2], bB + (uint32_t)((n2 * 16 * RPG + kk * 16) * 2));
#pragma unroll
            for (int mi = 0; mi < 4; mi++) {
                mma_f16(acc[mi][0], af[mi], bfq[0]);
                mma_f16(acc[mi][1], af[mi], bfq[0] + 2);
                mma_f16(acc[mi][2], af[mi], bfq[1]);
                mma_f16(acc[mi][3], af[mi], bfq[1] + 2);
            }
        }
    }

#pragma unroll
    for (int mi = 0; mi < 4; mi++) {
        const int r0 = bm + wm * 64 + mi * 16 + g;
#pragma unroll
        for (int ni = 0; ni < 4; ni++) {
            const int col = bn + wn * 32 + ni * 8 + c * 2;
            const float bx = __ldg(bias + col);
            const float by = __ldg(bias + col + 1);
            __half2 v0 = __floats2half2_rn(acc[mi][ni][0] + bx, acc[mi][ni][1] + by);
            __half2 v1 = __floats2half2_rn(acc[mi][ni][2] + bx, acc[mi][ni][3] + by);
            *(__half2*)(C + (size_t)r0 * E3 + col) = v0;
            *(__half2*)(C + (size_t)(r0 + 8) * E3 + col) = v1;
        }
    }
}

// ---------------------------------------------------------------------------
// Kernel B: flash attention (R16 winner, frozen)
// 64-row q tile, 4 warps, 3-buffer KV ring, 1 barrier/tile,
// fp16 operands, fp32 accum, no online max, log2-domain scores + ex2,
// tensor-core softmax denominator via ones-column in V, heavy-first qt.
// ---------------------------------------------------------------------------
#define ATT_TH 4608                       // 64*72 halves per buffer
#define NKV 3
#define QPOFF (2 * NKV * ATT_TH)          // after K[3] and V[3]
#define ATT_SMEM ((QPOFF + ATT_TH) * 2)   // 64512 bytes

__global__ __launch_bounds__(128, 3) void attn_h(
    const __half* __restrict__ qkv,
    const int* __restrict__ lens,
    float* __restrict__ out)
{
    extern __shared__ __half smh[];
    __half* QP = smh + QPOFF;

    const int tid  = threadIdx.x;
    const int wid  = tid >> 5;
    const int lane = tid & 31;
    const int g = lane >> 2;
    const int c = lane & 3;

    const int qt = (int)(gridDim.x - 1 - blockIdx.x);
    const int h  = blockIdx.y;
    const int b  = blockIdx.z;
    const int L  = get_len(lens, b);
    const int qbase = qt * 64;

    float* outp = out + ((size_t)(b * SEQ + qbase)) * EMB + h * DHEAD;

    if (qbase >= L) {
        float4 z = make_float4(0.f, 0.f, 0.f, 0.f);
#pragma unroll
        for (int t = 0; t < 8; t++) {
            int idx = t * 128 + tid;
            int row = idx >> 4, c4 = (idx & 15) << 2;
            *(float4*)(outp + (size_t)row * EMB + c4) = z;
        }
        return;
    }

    {
        const __half* qgp = qkv + ((size_t)(b * SEQ + qbase)) * E3 + h * DHEAD;
#pragma unroll
        for (int t = 0; t < 4; t++) {
            int idx = t * 128 + tid;
            int row = idx >> 3, ch = (idx & 7) << 3;
            *(uint4*)&QP[row * 72 + ch] = *(const uint4*)(qgp + (size_t)row * E3 + ch);
        }
    }

    const uint32_t sm_u = smem_u32(smh);
    const uint32_t QP_u = smem_u32(QP);
    const uint32_t Pw_u = QP_u + (uint32_t)(wid * 16 * 72) * 2;

    {
#pragma unroll
        for (int t = 0; t < 2; t++) {
            int idx = t * 128 + tid;
            if (idx < NKV * 64) {
                const uint32_t vbase = sm_u
                    + (uint32_t)((NKV + (idx >> 6)) * ATT_TH) * 2;
                const uint32_t addr = vbase + (uint32_t)(((idx & 63) * 72 + 64) * 2);
                asm volatile("st.shared.v4.b32 [%0], {%1,%2,%3,%4};"
                             :: "r"(addr), "r"(0x3C00u), "r"(0u), "r"(0u), "r"(0u)
                             : "memory");
            }
        }
    }
    __syncthreads();

    const uint32_t a_off = ((uint32_t)((lane & 15) * 72 + ((lane >> 4) << 3))) * 2;
    const uint32_t k_off = ((uint32_t)(((lane & 7) + ((lane >> 4) << 3)) * 72
                                       + (((lane >> 3) & 1) << 3))) * 2;
    const uint32_t ones_row_off = ((uint32_t)((lane & 15) * 72 + 64)) * 2;

    uint32_t qf[4][4];
    {
        const __half2 qs = __float2half2_rn(0.04508422f);   // log2(e)/32
#pragma unroll
        for (int kk = 0; kk < 4; kk++) {
            ldsm_x4(qf[kk], Pw_u + a_off + kk * 32);
#pragma unroll
            for (int r = 0; r < 4; r++)
                qf[kk][r] = h2_bits(__hmul2(bits_h2(qf[kk][r]), qs));
        }
    }

    const int ktmax = min(qt, (L - 1) >> 6);

#define KV_LOAD(kt, buf)                                                        \
    {                                                                           \
        const __half* kgp = qkv + ((size_t)(b * SEQ + (kt) * 64)) * E3          \
                            + EMB + h * DHEAD;                                  \
        const uint32_t dK = sm_u + (uint32_t)((buf) * ATT_TH) * 2;              \
        const uint32_t dV = sm_u + (uint32_t)((NKV + (buf)) * ATT_TH) * 2;      \
        _Pragma("unroll")                                                       \
        for (int t = 0; t < 8; t++) {                                           \
            int idx = t * 128 + tid;                                            \
            if (idx < 512) {                                                    \
                int row = idx >> 3, ch = (idx & 7) << 3;                        \
                cp16(dK + (row * 72 + ch) * 2, kgp + (size_t)row * E3 + ch);    \
            } else {                                                            \
                int jdx = idx - 512;                                            \
                int row = jdx >> 3, ch = (jdx & 7) << 3;                        \
                cp16(dV + (row * 72 + ch) * 2,                                  \
                     kgp + (size_t)row * E3 + EMB + ch);                        \
            }                                                                   \
        }                                                                       \
        asm volatile("cp.async.commit_group;" ::: "memory");                    \
    }

    KV_LOAD(0, 0);

    float lacc[4] = {0.f, 0.f, 0.f, 0.f};
    float oacc[8][4];
#pragma unroll
    for (int dt = 0; dt < 8; dt++)
#pragma unroll
        for (int r = 0; r < 4; r++) oacc[dt][r] = 0.f;

    __half* Pw = QP + (wid * 16) * 72;
    int buf = 0, nbuf = 1;

#pragma unroll 1
    for (int kt = 0; kt <= ktmax; kt++) {
        if (kt < ktmax) KV_LOAD(kt + 1, nbuf);
        if (kt < ktmax) asm volatile("cp.async.wait_group 1;" ::: "memory");
        else            asm volatile("cp.async.wait_group 0;" ::: "memory");
        __syncthreads();   // single barrier per tile (3-ring makes reuse safe)

        const uint32_t Kp_u = sm_u + (uint32_t)(buf * ATT_TH) * 2;
        const uint32_t Vp_u = sm_u + (uint32_t)((NKV + buf) * ATT_TH) * 2;

        float sacc[8][4];
#pragma unroll
        for (int nt = 0; nt < 8; nt++)
#pragma unroll
            for (int r = 0; r < 4; r++) sacc[nt][r] = 0.f;

#pragma unroll
        for (int kk = 0; kk < 4; kk++) {
#pragma unroll
            for (int nt2 = 0; nt2 < 4; nt2++) {
                uint32_t bf4[4];
                ldsm_x4(bf4, Kp_u + k_off + (uint32_t)(nt2 * 2304 + kk * 32));
                mma_f16(sacc[2 * nt2],     qf[kk], bf4);
                mma_f16(sacc[2 * nt2 + 1], qf[kk], bf4 + 2);
            }
        }

        if (kt == qt) {
            const int lr0 = wid * 16 + g;
            const int lr1 = lr0 + 8;
#pragma unroll
            for (int nt = 0; nt < 8; nt++) {
                const int col0 = nt * 8 + 2 * c;
                if (col0 > lr0)     sacc[nt][0] = -1e30f;
                if (col0 + 1 > lr0) sacc[nt][1] = -1e30f;
                if (col0 > lr1)     sacc[nt][2] = -1e30f;
                if (col0 + 1 > lr1) sacc[nt][3] = -1e30f;
            }
        }

#pragma unroll
        for (int nt = 0; nt < 8; nt++) {
            const float p0 = ex2f(sacc[nt][0]);
            const float p1 = ex2f(sacc[nt][1]);
            const float p2 = ex2f(sacc[nt][2]);
            const float p3 = ex2f(sacc[nt][3]);
            *(__half2*)&Pw[g * 72 + nt * 8 + 2 * c]       = __floats2half2_rn(p0, p1);
            *(__half2*)&Pw[(g + 8) * 72 + nt * 8 + 2 * c] = __floats2half2_rn(p2, p3);
        }
        __syncwarp();

#pragma unroll
        for (int kk = 0; kk < 4; kk++) {
            uint32_t pf[4];
            ldsm_x4(pf, Pw_u + a_off + kk * 32);
#pragma unroll
            for (int dtp = 0; dtp < 4; dtp++) {
                uint32_t bf4[4];
                ldsm_x4_t(bf4, Vp_u + a_off + (uint32_t)(kk * 2304 + dtp * 32));
                mma_f16(oacc[2 * dtp],     pf, bf4);
                mma_f16(oacc[2 * dtp + 1], pf, bf4 + 2);
            }
            uint32_t bo[2];
            ldsm_x2_t(bo, Vp_u + ones_row_off + (uint32_t)(kk * 2304));
            mma_f16(lacc, pf, bo);
        }

        buf = nbuf;
        nbuf = (nbuf == NKV - 1) ? 0 : nbuf + 1;
    }

    const float l0 = __shfl_sync(0xFFFFFFFF, lacc[0], lane & ~3);
    const float l1 = __shfl_sync(0xFFFFFFFF, lacc[2], lane & ~3);
    const float inv0 = 1.0f / l0;
    const float inv1 = 1.0f / l1;
    const int q0row = qbase + wid * 16 + g;
    const int q1row = q0row + 8;
    const bool v0 = (q0row < L);
    const bool v1 = (q1row < L);
    float* o0 = out + ((size_t)(b * SEQ + q0row)) * EMB + h * DHEAD;
    float* o1 = out + ((size_t)(b * SEQ + q1row)) * EMB + h * DHEAD;
#pragma unroll
    for (int dt = 0; dt < 8; dt++) {
        const int col = dt * 8 + 2 * c;
        float2 r0 = v0 ? make_float2(oacc[dt][0] * inv0, oacc[dt][1] * inv0)
                       : make_float2(0.f, 0.f);
        float2 r1 = v1 ? make_float2(oacc[dt][2] * inv1, oacc[dt][3] * inv1)
                       : make_float2(0.f, 0.f);
        *(float2*)(o0 + col) = r0;
        *(float2*)(o1 + col) = r1;
    }
}

// ---------------------------------------------------------------------------
// Launch
// ---------------------------------------------------------------------------
extern "C" void kernel_launch(void* const* d_in, const int* in_sizes, int n_in,
                              void* d_out, int out_size) {
    const float* x = nullptr;
    const int*   l = nullptr;
    const float* W = nullptr;
    const float* bias = nullptr;
    for (int i = 0; i < n_in; i++) {
        switch (in_sizes[i]) {
            case 8388608: x    = (const float*)d_in[i]; break;
            case 8:       l    = (const int*)d_in[i];   break;
            case 3145728: W    = (const float*)d_in[i]; break;
            case 3072:    bias = (const float*)d_in[i]; break;
            default: break;
        }
    }
    float* out = (float*)d_out;

    __half *xh = nullptr, *wh = nullptr, *qkvh = nullptr;
    cudaGetSymbolAddress((void**)&xh,   g_xh);
    cudaGetSymbolAddress((void**)&wh,   g_wh);
    cudaGetSymbolAddress((void**)&qkvh, g_qkvh);

    static bool attr_set = false;
    if (!attr_set) {
        cudaFuncSetAttribute(qkv_gemm_h,
                             cudaFuncAttributeMaxDynamicSharedMemorySize,
                             SMEM_GEMM_TOTAL);
        cudaFuncSetAttribute(attn_h,
                             cudaFuncAttributeMaxDynamicSharedMemorySize,
                             ATT_SMEM);
        attr_set = true;
    }

    // fp32 -> fp16 conversion of x (valid rows only) and W (single launch)
    {
        const int total = N4X + N4W;
        to_half_both<<<(total + 255) / 256, 256>>>(
            (const float4*)x, (uint2*)xh, (const float4*)W, (uint2*)wh, l);
    }

    dim3 gg(E3 / BN, (BATCH * SEQ) / BM);     // (24, 64)
    qkv_gemm_h<<<gg, 256, SMEM_GEMM_TOTAL>>>(xh, wh, bias, l, qkvh);

    dim3 ga(SEQ / 64, NHEAD, BATCH);          // (16, 16, 8)
    attn_h<<<ga, 128, ATT_SMEM>>>(qkvh, l, out);
}